// round 14
// baseline (speedup 1.0000x reference)
#include <cuda_runtime.h>
#include <cuda_bf16.h>
#include <mma.h>
#include <math.h>

using namespace nvcuda;

// ---------------------------------------------------------------------------
// TransformerCell: out = LN(relu(MHA(q=h, kv=concat(c,h,e,s), 8 heads)))
// Factorized exact algebra; GEMMs on wmma bf16 (HMMA) with hi/lo split
// (3-product MMA, ~1e-5 rel err). cp.async double-buffered mainloop.
//   qp   = (h @ Wq^T + bq) / 8                  [N,512]   (tensor, split out)
//   qt_h = qp_h @ WkT_h^T                       [N,8,512] (tensor, fp32 out)
//   attn core (SIMT fp32, 512 thr) -> w split   [N,8,512]
//   o_h  = w_h @ Wv_h^T + bv_h                  [N,512]   (tensor, split out)
//   y    = o @ Wo^T + bo                        [N,512]   (tensor, fp32 out)
//   out = LN(relu(y))
// ---------------------------------------------------------------------------

#define NB    8192
#define DIM   512
#define HEADS 8
#define KCTX  35

typedef unsigned long long u64;
typedef unsigned int       u32;

// ---------------- scratch (device globals; no runtime allocation) ----------
__device__ __align__(16) __nv_bfloat16 g_h_hi [NB * DIM];
__device__ __align__(16) __nv_bfloat16 g_h_lo [NB * DIM];
__device__ __align__(16) __nv_bfloat16 g_wq_hi[DIM * DIM];
__device__ __align__(16) __nv_bfloat16 g_wq_lo[DIM * DIM];
__device__ __align__(16) __nv_bfloat16 g_wkT_hi[DIM * DIM];   // [h][512][64] K-major
__device__ __align__(16) __nv_bfloat16 g_wkT_lo[DIM * DIM];
__device__ __align__(16) __nv_bfloat16 g_wv_hi[DIM * DIM];
__device__ __align__(16) __nv_bfloat16 g_wv_lo[DIM * DIM];
__device__ __align__(16) __nv_bfloat16 g_wo_hi[DIM * DIM];
__device__ __align__(16) __nv_bfloat16 g_wo_lo[DIM * DIM];
__device__ __align__(16) __nv_bfloat16 g_qp_hi[NB * DIM];
__device__ __align__(16) __nv_bfloat16 g_qp_lo[NB * DIM];
__device__ __align__(16) float         g_qt  [NB * HEADS * DIM];   // 128 MB
__device__ __align__(16) __nv_bfloat16 g_w_hi[NB * HEADS * DIM];   // 64 MB
__device__ __align__(16) __nv_bfloat16 g_w_lo[NB * HEADS * DIM];   // 64 MB
__device__ __align__(16) __nv_bfloat16 g_o_hi[NB * DIM];
__device__ __align__(16) __nv_bfloat16 g_o_lo[NB * DIM];
__device__ __align__(16) float         g_y   [NB * DIM];

// split fp32 -> bf16 hi + bf16 lo (lo = rn(residual))
__device__ __forceinline__ void split1(float v, __nv_bfloat16& hi, __nv_bfloat16& lo) {
    hi = __float2bfloat16(v);
    lo = __float2bfloat16(v - __bfloat162float(hi));
}
__device__ __forceinline__ void split_store4(__nv_bfloat16* hp, __nv_bfloat16* lp, float4 f) {
    union { __nv_bfloat16 b[4]; uint2 u; } H, L;
    split1(f.x, H.b[0], L.b[0]);
    split1(f.y, H.b[1], L.b[1]);
    split1(f.z, H.b[2], L.b[2]);
    split1(f.w, H.b[3], L.b[3]);
    *(uint2*)hp = H.u;
    *(uint2*)lp = L.u;
}

__device__ __forceinline__ u32 smem_u32(const void* p) {
    u32 a;
    asm("{ .reg .u64 t; cvta.to.shared.u64 t, %1; cvt.u32.u64 %0, t; }"
        : "=r"(a) : "l"(p));
    return a;
}
__device__ __forceinline__ void cpasync16(u32 dst, const void* src) {
    asm volatile("cp.async.cg.shared.global [%0], [%1], 16;"
                 :: "r"(dst), "l"(src) : "memory");
}
#define CP_COMMIT() asm volatile("cp.async.commit_group;" ::: "memory")

// ---------------------------------------------------------------------------
// split conversion kernels
// ---------------------------------------------------------------------------
__global__ void __launch_bounds__(256)
splitF32(const float* __restrict__ x, __nv_bfloat16* __restrict__ hi,
         __nv_bfloat16* __restrict__ lo)
{
    const int i = blockIdx.x * 256 + threadIdx.x;   // float4 index
    float4 v = ((const float4*)x)[i];
    split_store4(hi + 4 * (long)i, lo + 4 * (long)i, v);
}

// WkT[h][n][k] = split(Wk[h*64+k][n]); flat t = h*32768 + n*64 + k
__global__ void __launch_bounds__(256)
splitWkT(const float* __restrict__ Wk, __nv_bfloat16* __restrict__ hi,
         __nv_bfloat16* __restrict__ lo)
{
    const int t = blockIdx.x * 256 + threadIdx.x;
    const int k = t & 63, n = (t >> 6) & 511, h = t >> 15;
    float v = Wk[(h * 64 + k) * DIM + n];
    __nv_bfloat16 a, b;
    split1(v, a, b);
    hi[t] = a; lo[t] = b;
}

// ---------------------------------------------------------------------------
// wmma bf16 GEMM, hi/lo split (3 products), cp.async double buffer.
//   C[m, z*cz + bn + j] = (sum_k A[m,k]*B[n,k] + bias) * alpha
// Block: 256 thr = 8 warps (4m x 2n); tile M=128, N=BN, BK=32.
// SMEM rows padded to 40 bf16 (80 B, 16B multiple). Two stages.
// ---------------------------------------------------------------------------
template <int BN, bool SPLIT_OUT>
__global__ void __launch_bounds__(256)
wmmaGemm(const __nv_bfloat16* __restrict__ aHi, const __nv_bfloat16* __restrict__ aLo,
         int lda, int az,
         const __nv_bfloat16* __restrict__ bHi, const __nv_bfloat16* __restrict__ bLo,
         int ldb, int bz,
         const float* __restrict__ bias, int biasz,
         float* __restrict__ cF,
         __nv_bfloat16* __restrict__ cHi, __nv_bfloat16* __restrict__ cLo,
         int ldc, long cz,
         int K, float alpha)
{
    extern __shared__ __align__(16) char smem[];
    constexpr int A_SZ  = 128 * 40 * 2;               // bytes, one matrix
    constexpr int B_SZ  = BN * 40 * 2;
    constexpr int STAGE = 2 * A_SZ + 2 * B_SZ;
    constexpr int OFF_BIAS = 0;
    constexpr int OFF_T    = 1024;
    constexpr int WN    = BN / 2;
    constexpr int NFRAG = WN / 16;

    const u32 sb  = smem_u32(smem);
    const int tid = threadIdx.x;
    const int wid = tid >> 5;
    const int bm  = blockIdx.y * 128;
    const int bn  = blockIdx.x * BN;
    const int z   = blockIdx.z;
    const int wm  = (wid >> 1) * 32;
    const int wn  = (wid & 1) * WN;

    aHi += (long)z * az;  aLo += (long)z * az;
    bHi += (long)z * bz;  bLo += (long)z * bz;

    if (tid < BN) {
        float bvv = bias ? bias[(long)z * biasz + bn + tid] : 0.f;
        *(float*)(smem + OFF_BIAS + tid * 4) = bvv;
    }

#define LOAD_CHUNK(st, kOff)                                                   \
    {                                                                          \
        const u32 aHiS = sb + OFF_T + (st) * STAGE;                            \
        const u32 aLoS = aHiS + A_SZ;                                          \
        const u32 bHiS = aLoS + A_SZ;                                          \
        const u32 bLoS = bHiS + B_SZ;                                          \
        _Pragma("unroll")                                                      \
        for (int i = 0; i < 2; i++) {                                          \
            int t = tid + 256 * i;                                             \
            int r = t >> 2, cq = t & 3;                                        \
            const long go = (long)(bm + r) * lda + (kOff) + cq * 8;            \
            cpasync16(aHiS + r * 80 + cq * 16, aHi + go);                      \
            cpasync16(aLoS + r * 80 + cq * 16, aLo + go);                      \
        }                                                                      \
        _Pragma("unroll")                                                      \
        for (int i = 0; i < BN / 64; i++) {                                    \
            int t = tid + 256 * i;                                             \
            int r = t >> 2, cq = t & 3;                                        \
            const long go = (long)(bn + r) * ldb + (kOff) + cq * 8;            \
            cpasync16(bHiS + r * 80 + cq * 16, bHi + go);                      \
            cpasync16(bLoS + r * 80 + cq * 16, bLo + go);                      \
        }                                                                      \
    }

    wmma::fragment<wmma::accumulator, 16, 16, 16, float> acc[2][NFRAG];
#pragma unroll
    for (int mi = 0; mi < 2; mi++)
#pragma unroll
        for (int ni = 0; ni < NFRAG; ni++) wmma::fill_fragment(acc[mi][ni], 0.f);

    const int nChunks = K >> 5;                       // BK = 32
    LOAD_CHUNK(0, 0);
    CP_COMMIT();

    for (int kc = 0; kc < nChunks; kc++) {
        const int cur = kc & 1;
        if (kc + 1 < nChunks) {
            LOAD_CHUNK(!cur, (kc + 1) * 32);
            CP_COMMIT();
            asm volatile("cp.async.wait_group 1;" ::: "memory");
        } else {
            asm volatile("cp.async.wait_group 0;" ::: "memory");
        }
        __syncthreads();

        __nv_bfloat16* AsHi = (__nv_bfloat16*)(smem + OFF_T + cur * STAGE);
        __nv_bfloat16* AsLo = AsHi + 128 * 40;
        __nv_bfloat16* BsHi = AsLo + 128 * 40;
        __nv_bfloat16* BsLo = BsHi + BN * 40;

#pragma unroll
        for (int kf = 0; kf < 32; kf += 16) {
            wmma::fragment<wmma::matrix_a, 16, 16, 16, __nv_bfloat16, wmma::row_major> aH[2], aL[2];
#pragma unroll
            for (int mi = 0; mi < 2; mi++) {
                wmma::load_matrix_sync(aH[mi], AsHi + (wm + mi * 16) * 40 + kf, 40);
                wmma::load_matrix_sync(aL[mi], AsLo + (wm + mi * 16) * 40 + kf, 40);
            }
#pragma unroll
            for (int ni = 0; ni < NFRAG; ni++) {
                wmma::fragment<wmma::matrix_b, 16, 16, 16, __nv_bfloat16, wmma::col_major> bH, bL;
                wmma::load_matrix_sync(bH, BsHi + (wn + ni * 16) * 40 + kf, 40);
                wmma::load_matrix_sync(bL, BsLo + (wn + ni * 16) * 40 + kf, 40);
#pragma unroll
                for (int mi = 0; mi < 2; mi++) {
                    wmma::mma_sync(acc[mi][ni], aH[mi], bH, acc[mi][ni]);
                    wmma::mma_sync(acc[mi][ni], aH[mi], bL, acc[mi][ni]);
                    wmma::mma_sync(acc[mi][ni], aL[mi], bH, acc[mi][ni]);
                }
            }
        }
        __syncthreads();
    }
#undef LOAD_CHUNK

    // ---- epilogue: frags -> smem C overlay -> bias/alpha/(split) global ----
    float* Cs = (float*)(smem + OFF_T);
#pragma unroll
    for (int mi = 0; mi < 2; mi++)
#pragma unroll
        for (int ni = 0; ni < NFRAG; ni++)
            wmma::store_matrix_sync(Cs + (wm + mi * 16) * BN + wn + ni * 16,
                                    acc[mi][ni], BN, wmma::mem_row_major);
    __syncthreads();

    const float* bs = (const float*)(smem + OFF_BIAS);
    constexpr int NV = 128 * BN / 4 / 256;
#pragma unroll
    for (int i = 0; i < NV; i++) {
        int t = tid + 256 * i;
        int r = t / (BN / 4);
        int c4 = t % (BN / 4);
        float4 v = *(float4*)(Cs + r * BN + c4 * 4);
        v.x = (v.x + bs[c4 * 4 + 0]) * alpha;
        v.y = (v.y + bs[c4 * 4 + 1]) * alpha;
        v.z = (v.z + bs[c4 * 4 + 2]) * alpha;
        v.w = (v.w + bs[c4 * 4 + 3]) * alpha;
        const long off = (long)(bm + r) * ldc + (long)z * cz + bn + c4 * 4;
        if (SPLIT_OUT) split_store4(cHi + off, cLo + off, v);
        else           *(float4*)(cF + off) = v;
    }
}

// ---------------------------------------------------------------------------
// Attention core (SIMT fp32, packed f32x2): one CTA per batch, 512 threads.
// ctx (35x512 = 70KB) staged once in smem; w written as SPLIT bf16.
//  Phase B: warp (hp, jq) -> heads {2hp,2hp+1}, j-quarter (16 warps)
//  Softmax: warps 0..7, warp = head
//  Phase C: warp (hp, dq) -> heads {2hp,2hp+1}, 128-dim quarter
// ---------------------------------------------------------------------------
typedef unsigned long long uu64;
__device__ __forceinline__ uu64 pack2(float x, float y) {
    uu64 r; asm("mov.b64 %0, {%1, %2};" : "=l"(r) : "f"(x), "f"(y)); return r;
}
__device__ __forceinline__ void fma2(uu64& d, uu64 a, uu64 b) {
    asm("fma.rn.f32x2 %0, %1, %2, %0;" : "+l"(d) : "l"(a), "l"(b));
}
__device__ __forceinline__ float2 unpack2(uu64 v) {
    float2 f; asm("mov.b64 {%0, %1}, %2;" : "=f"(f.x), "=f"(f.y) : "l"(v)); return f;
}

__global__ void __launch_bounds__(512)
attn_core(const float* __restrict__ qt, const float* __restrict__ cc,
          const float* __restrict__ hv, const float* __restrict__ ev,
          const float* __restrict__ sv,
          __nv_bfloat16* __restrict__ whi, __nv_bfloat16* __restrict__ wlo)
{
    extern __shared__ __align__(16) float smbuf[];
    float* ctx   = smbuf;                    // [35][512]
    float* sc    = smbuf + KCTX * DIM;       // [8][35]
    float* attnw = sc + HEADS * KCTX;        // [8][35]

    const int n    = blockIdx.x;
    const int tid  = threadIdx.x;
    const int lane = tid & 31;
    const int warp = tid >> 5;

    // stage ctx
    {
        const float4* c4 = (const float4*)(cc + (long)n * 32 * DIM);
        float4* d4 = (float4*)ctx;
#pragma unroll 4
        for (int i = tid; i < 32 * DIM / 4; i += 512) d4[i] = c4[i];
        for (int i = tid; i < 3 * DIM / 4; i += 512) {
            const int r = i >> 7;
            const int v = i & 127;
            const float* src = (r == 0) ? hv : (r == 1) ? ev : sv;
            ((float4*)(ctx + (32 + r) * DIM))[v] =
                ((const float4*)(src + (long)n * DIM))[v];
        }
    }
    __syncthreads();

    const int hp = warp >> 2;
    const int h0 = hp * 2, h1 = h0 + 1;

    // Phase B: scores (16 warps: head-pair x j-quarter)
    {
        const float4* qa = (const float4*)(qt + (long)n * (HEADS * DIM) + h0 * DIM);
        const float4* qb = (const float4*)(qt + (long)n * (HEADS * DIM) + h1 * DIM);
        uu64 qa2[8], qb2[8];
#pragma unroll
        for (int i = 0; i < 4; i++) {
            float4 ra = qa[lane + 32 * i];
            float4 rb = qb[lane + 32 * i];
            qa2[2 * i] = pack2(ra.x, ra.y); qa2[2 * i + 1] = pack2(ra.z, ra.w);
            qb2[2 * i] = pack2(rb.x, rb.y); qb2[2 * i + 1] = pack2(rb.z, rb.w);
        }
        const int jq = warp & 3;
        const int jb = jq * 9;
        const int je = (jb + 9 < KCTX) ? jb + 9 : KCTX;
        for (int j = jb; j < je; j++) {
            const ulonglong2* xp = (const ulonglong2*)(ctx + j * DIM);
            uu64 p0 = 0ull, p1 = 0ull;
#pragma unroll
            for (int i = 0; i < 4; i++) {
                ulonglong2 x = xp[lane + 32 * i];
                fma2(p0, qa2[2 * i], x.x); fma2(p0, qa2[2 * i + 1], x.y);
                fma2(p1, qb2[2 * i], x.x); fma2(p1, qb2[2 * i + 1], x.y);
            }
            float2 f0 = unpack2(p0), f1 = unpack2(p1);
            float s0 = f0.x + f0.y, s1 = f1.x + f1.y;
#pragma unroll
            for (int o = 16; o; o >>= 1) {
                s0 += __shfl_xor_sync(0xffffffffu, s0, o);
                s1 += __shfl_xor_sync(0xffffffffu, s1, o);
            }
            if (lane == 0) { sc[h0 * KCTX + j] = s0; sc[h1 * KCTX + j] = s1; }
        }
    }
    __syncthreads();

    // Softmax (warps 0..7; warp = head)
    if (warp < HEADS) {
        const int hh = warp;
        float s1 = sc[hh * KCTX + lane];
        float s2 = (lane < 3) ? sc[hh * KCTX + 32 + lane] : -3.0e38f;
        float m = fmaxf(s1, s2);
#pragma unroll
        for (int o = 16; o; o >>= 1)
            m = fmaxf(m, __shfl_xor_sync(0xffffffffu, m, o));
        float e1 = expf(s1 - m);
        float e2 = (lane < 3) ? expf(s2 - m) : 0.f;
        float sum = e1 + e2;
#pragma unroll
        for (int o = 16; o; o >>= 1)
            sum += __shfl_xor_sync(0xffffffffu, sum, o);
        float inv = 1.f / sum;
        attnw[hh * KCTX + lane] = e1 * inv;
        if (lane < 3) attnw[hh * KCTX + 32 + lane] = e2 * inv;
    }
    __syncthreads();

    // Phase C: w = attn @ ctx (16 warps: head-pair x 128-dim quarter)
    {
        const int dq    = warp & 3;
        const int dbase = dq * 128;            // floats
        uu64 acc2[2][2];
        acc2[0][0] = acc2[0][1] = acc2[1][0] = acc2[1][1] = 0ull;

        for (int j = 0; j < KCTX; j++) {
            ulonglong2 x = ((const ulonglong2*)(ctx + j * DIM + dbase))[lane];
            uu64 a0d = pack2(attnw[h0 * KCTX + j], attnw[h0 * KCTX + j]);
            uu64 a1d = pack2(attnw[h1 * KCTX + j], attnw[h1 * KCTX + j]);
            fma2(acc2[0][0], a0d, x.x); fma2(acc2[0][1], a0d, x.y);
            fma2(acc2[1][0], a1d, x.x); fma2(acc2[1][1], a1d, x.y);
        }
        const long w0off = (long)n * (HEADS * DIM) + h0 * DIM + dbase + 4 * lane;
        const long w1off = (long)n * (HEADS * DIM) + h1 * DIM + dbase + 4 * lane;
        float2 a = unpack2(acc2[0][0]);
        float2 b = unpack2(acc2[0][1]);
        split_store4(whi + w0off, wlo + w0off, make_float4(a.x, a.y, b.x, b.y));
        float2 c0 = unpack2(acc2[1][0]);
        float2 d0 = unpack2(acc2[1][1]);
        split_store4(whi + w1off, wlo + w1off, make_float4(c0.x, c0.y, d0.x, d0.y));
    }
}

// ---------------------------------------------------------------------------
// relu + LayerNorm (ddof=1, eps added to STD). One warp per row.
// ---------------------------------------------------------------------------
__global__ void __launch_bounds__(256)
relu_ln(const float* __restrict__ y, const float* __restrict__ ln_a,
        const float* __restrict__ ln_b, float* __restrict__ out)
{
    const int lane = threadIdx.x & 31;
    const int warp = threadIdx.x >> 5;
    const int row  = blockIdx.x * 8 + warp;

    const float4* xr = (const float4*)(y + (long)row * DIM);
    float4 v[4];
    float sum = 0.f;
#pragma unroll
    for (int i = 0; i < 4; i++) {
        float4 x = xr[lane + 32 * i];
        x.x = fmaxf(x.x, 0.f); x.y = fmaxf(x.y, 0.f);
        x.z = fmaxf(x.z, 0.f); x.w = fmaxf(x.w, 0.f);
        v[i] = x;
        sum += x.x + x.y + x.z + x.w;
    }
#pragma unroll
    for (int o = 16; o; o >>= 1) sum += __shfl_xor_sync(0xffffffffu, sum, o);
    const float mean = sum * (1.f / (float)DIM);

    float ssq = 0.f;
#pragma unroll
    for (int i = 0; i < 4; i++) {
        float dx;
        dx = v[i].x - mean; ssq = fmaf(dx, dx, ssq);
        dx = v[i].y - mean; ssq = fmaf(dx, dx, ssq);
        dx = v[i].z - mean; ssq = fmaf(dx, dx, ssq);
        dx = v[i].w - mean; ssq = fmaf(dx, dx, ssq);
    }
#pragma unroll
    for (int o = 16; o; o >>= 1) ssq += __shfl_xor_sync(0xffffffffu, ssq, o);
    const float stddev = sqrtf(ssq * (1.f / (float)(DIM - 1)));
    const float inv = 1.f / (stddev + 1e-6f);

    float4* orow = (float4*)(out + (long)row * DIM);
    const float4* a4 = (const float4*)ln_a;
    const float4* b4 = (const float4*)ln_b;
#pragma unroll
    for (int i = 0; i < 4; i++) {
        const int idx = lane + 32 * i;
        float4 a = a4[idx], b = b4[idx], o4;
        o4.x = fmaf(a.x * inv, v[i].x - mean, b.x);
        o4.y = fmaf(a.y * inv, v[i].y - mean, b.y);
        o4.z = fmaf(a.z * inv, v[i].z - mean, b.z);
        o4.w = fmaf(a.w * inv, v[i].w - mean, b.w);
        orow[idx] = o4;
    }
}

// ---------------------------------------------------------------------------
extern "C" void kernel_launch(void* const* d_in, const int* in_sizes, int n_in,
                              void* d_out, int out_size)
{
    const float* c   = (const float*)d_in[0];
    const float* h   = (const float*)d_in[1];
    const float* e   = (const float*)d_in[2];
    const float* s   = (const float*)d_in[3];
    const float* Wq  = (const float*)d_in[4];
    const float* bq  = (const float*)d_in[5];
    const float* Wk  = (const float*)d_in[6];
    /* bk = d_in[7] unused: constant across softmax axis, drops exactly */
    const float* Wv  = (const float*)d_in[8];
    const float* bv  = (const float*)d_in[9];
    const float* Wo  = (const float*)d_in[10];
    const float* bo  = (const float*)d_in[11];
    const float* la  = (const float*)d_in[12];
    const float* lb  = (const float*)d_in[13];
    float* out = (float*)d_out;

    void *p;
    __nv_bfloat16 *hHi, *hLo, *wqHi, *wqLo, *wkHi, *wkLo, *wvHi, *wvLo, *woHi, *woLo;
    __nv_bfloat16 *qpHi, *qpLo, *wHi, *wLo, *oHi, *oLo;
    float *qt, *y;
    cudaGetSymbolAddress(&p, g_h_hi);  hHi  = (__nv_bfloat16*)p;
    cudaGetSymbolAddress(&p, g_h_lo);  hLo  = (__nv_bfloat16*)p;
    cudaGetSymbolAddress(&p, g_wq_hi); wqHi = (__nv_bfloat16*)p;
    cudaGetSymbolAddress(&p, g_wq_lo); wqLo = (__nv_bfloat16*)p;
    cudaGetSymbolAddress(&p, g_wkT_hi); wkHi = (__nv_bfloat16*)p;
    cudaGetSymbolAddress(&p, g_wkT_lo); wkLo = (__nv_bfloat16*)p;
    cudaGetSymbolAddress(&p, g_wv_hi); wvHi = (__nv_bfloat16*)p;
    cudaGetSymbolAddress(&p, g_wv_lo); wvLo = (__nv_bfloat16*)p;
    cudaGetSymbolAddress(&p, g_wo_hi); woHi = (__nv_bfloat16*)p;
    cudaGetSymbolAddress(&p, g_wo_lo); woLo = (__nv_bfloat16*)p;
    cudaGetSymbolAddress(&p, g_qp_hi); qpHi = (__nv_bfloat16*)p;
    cudaGetSymbolAddress(&p, g_qp_lo); qpLo = (__nv_bfloat16*)p;
    cudaGetSymbolAddress(&p, g_qt);    qt   = (float*)p;
    cudaGetSymbolAddress(&p, g_w_hi);  wHi  = (__nv_bfloat16*)p;
    cudaGetSymbolAddress(&p, g_w_lo);  wLo  = (__nv_bfloat16*)p;
    cudaGetSymbolAddress(&p, g_o_hi);  oHi  = (__nv_bfloat16*)p;
    cudaGetSymbolAddress(&p, g_o_lo);  oLo  = (__nv_bfloat16*)p;
    cudaGetSymbolAddress(&p, g_y);     y    = (float*)p;

    // smem sizes: 1024 + max(2 stages, C overlay)
    const int ST128 = 2 * (2 * 128 * 40 * 2 + 2 * 128 * 40 * 2);  // 81920
    const int ST64  = 2 * (2 * 128 * 40 * 2 + 2 * 64 * 40 * 2);   // 61440
    const int SM128 = 1024 + (ST128 > 128 * 128 * 4 ? ST128 : 128 * 128 * 4);
    const int SM64  = 1024 + (ST64  > 128 * 64 * 4  ? ST64  : 128 * 64 * 4);
    const int ATTN_SMEM = (KCTX * DIM + 2 * HEADS * KCTX) * (int)sizeof(float);

    cudaFuncSetAttribute(wmmaGemm<128, true>,
                         cudaFuncAttributeMaxDynamicSharedMemorySize, SM128);
    cudaFuncSetAttribute(wmmaGemm<128, false>,
                         cudaFuncAttributeMaxDynamicSharedMemorySize, SM128);
    cudaFuncSetAttribute(wmmaGemm<64, true>,
                         cudaFuncAttributeMaxDynamicSharedMemorySize, SM64);
    cudaFuncSetAttribute(attn_core,
                         cudaFuncAttributeMaxDynamicSharedMemorySize, ATTN_SMEM);

    // 0) conversions
    splitF32<<<NB * DIM / 4 / 256, 256>>>(h, hHi, hLo);
    splitF32<<<DIM * DIM / 4 / 256, 256>>>(Wq, wqHi, wqLo);
    splitF32<<<DIM * DIM / 4 / 256, 256>>>(Wv, wvHi, wvLo);
    splitF32<<<DIM * DIM / 4 / 256, 256>>>(Wo, woHi, woLo);
    splitWkT<<<DIM * DIM / 256, 256>>>(Wk, wkHi, wkLo);

    // 1) qp = (h @ Wq^T + bq)*0.125 -> split bf16
    wmmaGemm<128, true><<<dim3(4, 64, 1), 256, SM128>>>(
        hHi, hLo, DIM, 0, wqHi, wqLo, DIM, 0, bq, 0,
        (float*)0, qpHi, qpLo, DIM, 0, DIM, 0.125f);

    // 2) qt[n, h*512+d] = qp_h @ WkT_h^T  (z = head, K = 64) -> fp32
    wmmaGemm<128, false><<<dim3(4, 64, 8), 256, SM128>>>(
        qpHi, qpLo, DIM, 64, wkHi, wkLo, 64, 512 * 64, (const float*)0, 0,
        qt, (__nv_bfloat16*)0, (__nv_bfloat16*)0, HEADS * DIM, DIM, 64, 1.0f);

    // 3) attention core -> w split bf16
    attn_core<<<NB, 512, ATTN_SMEM>>>(qt, c, h, e, s, wHi, wLo);

    // 4) o[:, h*64..] = w_h @ Wv_h^T + bv_h (z = head) -> split bf16
    wmmaGemm<64, true><<<dim3(1, 64, 8), 256, SM64>>>(
        wHi, wLo, HEADS * DIM, DIM, wvHi, wvLo, DIM, 64 * DIM, bv, 64,
        (float*)0, oHi, oLo, DIM, 64, DIM, 1.0f);

    // 5) y = o @ Wo^T + bo -> fp32
    wmmaGemm<128, false><<<dim3(4, 64, 1), 256, SM128>>>(
        oHi, oLo, DIM, 0, woHi, woLo, DIM, 0, bo, 0,
        y, (__nv_bfloat16*)0, (__nv_bfloat16*)0, DIM, 0, DIM, 1.0f);

    // 6) out = LN(relu(y))
    relu_ln<<<NB / 8, 256>>>(y, la, lb, out);
}